// round 3
// baseline (speedup 1.0000x reference)
#include <cuda_runtime.h>

// GatedMemoryModule: out = g * softmax(x @ mem^T) @ mem + (1-g) * x,  g = sigmoid(x @ w + b)
// N = 1e6 rows, D = 128, MEM = 64 slots. FP32 throughout, packed f32x2 FMAs.

#define TN      128     // rows per CTA
#define DDIM    128     // feature dim
#define MSLOT   64      // memory slots
#define NTHREADS 256

// SMEM layout (float offsets). Padded strides chosen for bank-conflict freedom
// on the hot-loop access patterns (see analysis in commit message).
#define XS_STR  132
#define MS_STR  132
#define MT_STR  68
#define S_STR   129
#define OFF_XS  0
#define OFF_MS  (OFF_XS + TN * XS_STR)            // 16896
#define OFF_MT  (OFF_MS + MSLOT * MS_STR)         // 25344
#define OFF_S   (OFF_MT + DDIM * MT_STR)          // 34048
#define OFF_W   (OFF_S + MSLOT * S_STR)           // 42304
#define OFF_SC  (OFF_W + DDIM)                    // 42432  (g / sum)
#define OFF_OG  (OFF_SC + TN)                     // 42560  (1 - g)
#define SMEM_FLOATS (OFF_OG + TN)                 // 42688
#define SMEM_BYTES  (SMEM_FLOATS * 4)             // 170752

typedef unsigned long long ull;

__device__ __forceinline__ ull ffma2(ull a, ull b, ull c) {
    ull d;
    asm("fma.rn.f32x2 %0, %1, %2, %3;" : "=l"(d) : "l"(a), "l"(b), "l"(c));
    return d;
}
__device__ __forceinline__ ull pack2(float lo, float hi) {
    ull r;
    asm("mov.b64 %0, {%1, %2};" : "=l"(r) : "f"(lo), "f"(hi));
    return r;
}
__device__ __forceinline__ float2 unpack2(ull v) {
    float2 f;
    asm("mov.b64 {%0, %1}, %2;" : "=f"(f.x), "=f"(f.y) : "l"(v));
    return f;
}

extern __shared__ float sm[];

__global__ void __launch_bounds__(NTHREADS)
gated_memory_kernel(const float* __restrict__ x,
                    const float* __restrict__ mem,
                    const float* __restrict__ gw,
                    const float* __restrict__ gb,
                    float* __restrict__ out,
                    int Ntot)
{
    const int tid = threadIdx.x;
    const long n0 = (long)blockIdx.x * TN;

    // ---- Phase 0: stage X tile and memory into SMEM (coalesced float4) ----
    {
        const float4* x4 = (const float4*)x;
        #pragma unroll
        for (int i = tid; i < TN * DDIM / 4; i += NTHREADS) {
            int n  = i >> 5;      // 32 float4 per row
            int d4 = i & 31;
            float4 v = make_float4(0.f, 0.f, 0.f, 0.f);
            if (n0 + n < (long)Ntot) v = x4[(n0 + n) * 32 + d4];
            *(float4*)&sm[OFF_XS + n * XS_STR + 4 * d4] = v;
        }
        const float4* m4 = (const float4*)mem;
        #pragma unroll
        for (int i = tid; i < MSLOT * DDIM / 4; i += NTHREADS) {
            int m  = i >> 5;
            int d4 = i & 31;
            float4 v = m4[i];
            *(float4*)&sm[OFF_MS + m * MS_STR + 4 * d4] = v;
        }
        if (tid < DDIM) sm[OFF_W + tid] = gw[tid];
    }
    __syncthreads();

    // ---- Phase 1: build MT[k][m] = mem[m][k] via SMEM bounce ----
    #pragma unroll
    for (int i = tid; i < MSLOT * DDIM; i += NTHREADS) {
        int m = i & (MSLOT - 1);
        int k = i >> 6;
        sm[OFF_MT + k * MT_STR + m] = sm[OFF_MS + m * MS_STR + k];
    }
    __syncthreads();

    // ---- Phase 2: S[m][n] = sum_k x[n][k] * mem[m][k]  (FFMA2 pairs over m) ----
    {
        const int tm = tid & 7;    // m base = 8*tm   (8 m values = 4 pairs)
        const int tn = tid >> 3;   // n base = 4*tn   (4 n values)
        ull acc[4][4];             // [mpair][n]
        #pragma unroll
        for (int p = 0; p < 4; p++)
            #pragma unroll
            for (int i = 0; i < 4; i++) acc[p][i] = 0ull;

        #pragma unroll 2
        for (int k = 0; k < DDIM; k++) {
            // 8 consecutive MT values for this thread's m-range: 2x LDS.128
            float4 a = *(const float4*)&sm[OFF_MT + k * MT_STR + 8 * tm];
            float4 b = *(const float4*)&sm[OFF_MT + k * MT_STR + 8 * tm + 4];
            ull mv[4];
            mv[0] = pack2(a.x, a.y);
            mv[1] = pack2(a.z, a.w);
            mv[2] = pack2(b.x, b.y);
            mv[3] = pack2(b.z, b.w);
            #pragma unroll
            for (int i = 0; i < 4; i++) {
                float xv = sm[OFF_XS + (4 * tn + i) * XS_STR + k];
                ull xd = pack2(xv, xv);
                #pragma unroll
                for (int p = 0; p < 4; p++)
                    acc[p][i] = ffma2(mv[p], xd, acc[p][i]);
            }
        }
        #pragma unroll
        for (int p = 0; p < 4; p++)
            #pragma unroll
            for (int i = 0; i < 4; i++) {
                float2 f = unpack2(acc[p][i]);
                int m = 8 * tm + 2 * p;
                int n = 4 * tn + i;
                sm[OFF_S + m * S_STR + n]       = f.x;
                sm[OFF_S + (m + 1) * S_STR + n] = f.y;
            }
    }
    __syncthreads();

    // ---- Phase 3: per-row gate + softmax stats (128 threads, one per row) ----
    if (tid < TN) {
        const int n = tid;
        float gd = 0.f;
        #pragma unroll
        for (int k = 0; k < DDIM; k += 4) {
            float4 xv = *(const float4*)&sm[OFF_XS + n * XS_STR + k];
            gd += xv.x * sm[OFF_W + k] + xv.y * sm[OFF_W + k + 1]
                + xv.z * sm[OFF_W + k + 2] + xv.w * sm[OFF_W + k + 3];
        }
        gd += gb[0];
        float g = 1.f / (1.f + __expf(-gd));

        float mx = -1e30f;
        #pragma unroll 8
        for (int m = 0; m < MSLOT; m++)
            mx = fmaxf(mx, sm[OFF_S + m * S_STR + n]);
        float sum = 0.f;
        #pragma unroll 8
        for (int m = 0; m < MSLOT; m++) {
            float e = __expf(sm[OFF_S + m * S_STR + n] - mx);
            sm[OFF_S + m * S_STR + n] = e;   // keep raw exp; 1/sum folded below
            sum += e;
        }
        sm[OFF_SC + n] = g / sum;
        sm[OFF_OG + n] = 1.f - g;
    }
    __syncthreads();

    // ---- Phase 4: R[n][d] = sum_m E[m][n] * mem[m][d]; out = (1-g)x + (g/sum)R ----
    {
        const int td = tid & 7;    // d base = 16*td  (16 d values = 8 pairs)
        const int tn = tid >> 3;   // n base = 4*tn
        ull acc[4][8];             // [n][dpair]
        #pragma unroll
        for (int i = 0; i < 4; i++)
            #pragma unroll
            for (int p = 0; p < 8; p++) acc[i][p] = 0ull;

        #pragma unroll 2
        for (int m = 0; m < MSLOT; m++) {
            ull ms[8];
            #pragma unroll
            for (int q = 0; q < 4; q++) {
                float4 v = *(const float4*)&sm[OFF_MS + m * MS_STR + 16 * td + 4 * q];
                ms[2 * q]     = pack2(v.x, v.y);
                ms[2 * q + 1] = pack2(v.z, v.w);
            }
            #pragma unroll
            for (int i = 0; i < 4; i++) {
                float av = sm[OFF_S + m * S_STR + 4 * tn + i];
                ull ad = pack2(av, av);
                #pragma unroll
                for (int p = 0; p < 8; p++)
                    acc[i][p] = ffma2(ad, ms[p], acc[i][p]);
            }
        }

        #pragma unroll
        for (int i = 0; i < 4; i++) {
            const int nl = 4 * tn + i;
            const long n = n0 + nl;
            if (n < (long)Ntot) {
                const float sc = sm[OFF_SC + nl];
                const float og = sm[OFF_OG + nl];
                #pragma unroll
                for (int p = 0; p < 8; p++) {
                    float2 r = unpack2(acc[i][p]);
                    int d = 16 * td + 2 * p;
                    float xa = sm[OFF_XS + nl * XS_STR + d];
                    float xb = sm[OFF_XS + nl * XS_STR + d + 1];
                    float2 o;
                    o.x = og * xa + sc * r.x;
                    o.y = og * xb + sc * r.y;
                    *(float2*)&out[n * DDIM + d] = o;
                }
            }
        }
    }
}

extern "C" void kernel_launch(void* const* d_in, const int* in_sizes, int n_in,
                              void* d_out, int out_size)
{
    const float* x   = (const float*)d_in[0];
    const float* mem = (const float*)d_in[1];
    const float* gw  = (const float*)d_in[2];
    const float* gb  = (const float*)d_in[3];
    float* out = (float*)d_out;

    const int Ntot = in_sizes[0] / DDIM;
    const int grid = (Ntot + TN - 1) / TN;

    cudaFuncSetAttribute(gated_memory_kernel,
                         cudaFuncAttributeMaxDynamicSharedMemorySize, SMEM_BYTES);
    gated_memory_kernel<<<grid, NTHREADS, SMEM_BYTES>>>(x, mem, gw, gb, out, Ntot);
}

// round 9
// speedup vs baseline: 4.2479x; 4.2479x over previous
#include <cuda_runtime.h>
#include <cuda_bf16.h>
#include <cstdint>

// GatedMemoryModule via classic mma.sync (HMMA, sm_80+ PTX — compiles at plain sm_103).
// out = g * softmax(x @ mem^T) @ mem + (1-g) * x,   g = sigmoid(x @ w + b)
// bf16x3 split (hi*hi + hi*lo + lo*hi) for ~fp32 accuracy.
// Per CTA: 128 rows, 256 threads (8 warps x 16 rows). Softmax + operand conversion
// fully register-resident between the two GEMMs.
// R8 fix: Phase-0 staging wrote 8-byte bf16 packs at 16-byte strides (overflowed
// the padded rows, corrupting operand tiles -> NaN). Now q*8.

#define TN       128
#define DDIM     128
#define MSLOT    64
#define NTHREADS 256

// SMEM (bytes). bf16 row strides padded so fragment LDS is conflict-free:
// stride % 128 == 16 bytes  ->  8 rows land on banks {0,4,8,...,28}+quad{0..3}.
#define XSTR   272      // 136 bf16 per row (128 used)
#define MSTR   272
#define MTSTR  144      // 72 bf16 per row (64 used)
#define OFF_XH   0                          // 128*272 = 34816
#define OFF_XL   34816                      // 34816
#define OFF_MH   69632                      // 64*272 = 17408
#define OFF_ML   87040
#define OFF_MTH  104448                     // 128*144 = 18432
#define OFF_MTL  122880                     // -> 141312
#define OFF_GATE 141312                     // 128 f32 (g per row)
#define OFF_GW   141824                     // 128 f32
#define OFF_STAGE 69632                     // reuse MH..MTL after GEMM2: 128*132*4 = 67584
#define STG_STR  132
#define SMEM_BYTES 142336

__device__ __forceinline__ void mma16816(float* d, const uint32_t* a, const uint32_t* b) {
    asm volatile(
        "mma.sync.aligned.m16n8k16.row.col.f32.bf16.bf16.f32 "
        "{%0,%1,%2,%3}, {%4,%5,%6,%7}, {%8,%9}, {%0,%1,%2,%3};"
        : "+f"(d[0]), "+f"(d[1]), "+f"(d[2]), "+f"(d[3])
        : "r"(a[0]), "r"(a[1]), "r"(a[2]), "r"(a[3]), "r"(b[0]), "r"(b[1]));
}
__device__ __forceinline__ void split2(float v, __nv_bfloat16& h, __nv_bfloat16& l) {
    h = __float2bfloat16(v);
    l = __float2bfloat16(v - __bfloat162float(h));
}
__device__ __forceinline__ uint32_t packbf(__nv_bfloat16 a, __nv_bfloat16 b) {
    __nv_bfloat162 p; p.x = a; p.y = b;
    return *(uint32_t*)&p;
}

extern __shared__ char smc[];

__global__ void __launch_bounds__(NTHREADS, 1)
gated_memory_hmma(const float* __restrict__ x, const float* __restrict__ mem,
                  const float* __restrict__ gw, const float* __restrict__ gb,
                  float* __restrict__ out, int Ntot)
{
    const int tid = threadIdx.x;
    const int wid = tid >> 5;
    const int lane = tid & 31;
    const int qid = lane >> 2;          // fragment group id (row within tile)
    const int qtr = lane & 3;           // thread-in-group (col pair selector)
    const long long n0 = (long long)blockIdx.x * TN;

    // ================= Phase 0: stage operands (global -> SMEM, bf16 hi/lo) =========
    {
        const float4* x4 = (const float4*)x;
        #pragma unroll
        for (int i = tid; i < TN * DDIM / 4; i += NTHREADS) {
            int n = i >> 5, q = i & 31;
            float4 v = make_float4(0.f, 0.f, 0.f, 0.f);
            if (n0 + n < (long long)Ntot) v = x4[(n0 + n) * (DDIM / 4) + q];
            float vv[4] = {v.x, v.y, v.z, v.w};
            __nv_bfloat16 h[4], l[4];
            #pragma unroll
            for (int j = 0; j < 4; j++) split2(vv[j], h[j], l[j]);
            char* ph = smc + OFF_XH + n * XSTR + q * 8;   // 4 bf16 = 8 bytes
            char* pl = smc + OFF_XL + n * XSTR + q * 8;
            ((uint32_t*)ph)[0] = packbf(h[0], h[1]); ((uint32_t*)ph)[1] = packbf(h[2], h[3]);
            ((uint32_t*)pl)[0] = packbf(l[0], l[1]); ((uint32_t*)pl)[1] = packbf(l[2], l[3]);
        }
        const float4* m4 = (const float4*)mem;
        #pragma unroll
        for (int i = tid; i < MSLOT * DDIM / 4; i += NTHREADS) {
            int m = i >> 5, q = i & 31;
            float4 v = m4[i];
            float vv[4] = {v.x, v.y, v.z, v.w};
            __nv_bfloat16 h[4], l[4];
            #pragma unroll
            for (int j = 0; j < 4; j++) split2(vv[j], h[j], l[j]);
            char* ph = smc + OFF_MH + m * MSTR + q * 8;   // 4 bf16 = 8 bytes
            char* pl = smc + OFF_ML + m * MSTR + q * 8;
            ((uint32_t*)ph)[0] = packbf(h[0], h[1]); ((uint32_t*)ph)[1] = packbf(h[2], h[3]);
            ((uint32_t*)pl)[0] = packbf(l[0], l[1]); ((uint32_t*)pl)[1] = packbf(l[2], l[3]);
            #pragma unroll
            for (int j = 0; j < 4; j++) {   // transposed tile memT[d][m]
                int d = 4 * q + j;
                *(__nv_bfloat16*)(smc + OFF_MTH + d * MTSTR + m * 2) = h[j];
                *(__nv_bfloat16*)(smc + OFF_MTL + d * MTSTR + m * 2) = l[j];
            }
        }
        if (tid < DDIM) *(float*)(smc + OFF_GW + 4 * tid) = gw[tid];
    }
    __syncthreads();

    // ================= gate: g[n] = sigmoid(x[n].w + b) ============================
    if (tid < TN) {
        float acc = 0.f;
        #pragma unroll 16
        for (int c = 0; c < DDIM; c += 2) {
            __nv_bfloat162 hv = *(__nv_bfloat162*)(smc + OFF_XH + tid * XSTR + c * 2);
            __nv_bfloat162 lv = *(__nv_bfloat162*)(smc + OFF_XL + tid * XSTR + c * 2);
            float2 wv = *(float2*)(smc + OFF_GW + 4 * c);
            acc += (__bfloat162float(hv.x) + __bfloat162float(lv.x)) * wv.x
                 + (__bfloat162float(hv.y) + __bfloat162float(lv.y)) * wv.y;
        }
        float g = 1.f / (1.f + __expf(-(acc + gb[0])));
        *(float*)(smc + OFF_GATE + 4 * tid) = g;
    }
    __syncthreads();

    const int r0 = wid * 16;            // this warp's row block

    // ================= GEMM1: S[16 x 64] = X @ Mem^T  (bf16x3) =====================
    float acc1[8][4];
    #pragma unroll
    for (int nt = 0; nt < 8; nt++)
        #pragma unroll
        for (int j = 0; j < 4; j++) acc1[nt][j] = 0.f;

    #pragma unroll
    for (int ks = 0; ks < 8; ks++) {
        const int k0 = ks * 16;
        uint32_t ah[4], al[4];
        {
            const int r = r0 + qid, c = k0 + qtr * 2;
            ah[0] = *(uint32_t*)(smc + OFF_XH + r * XSTR + c * 2);
            ah[1] = *(uint32_t*)(smc + OFF_XH + (r + 8) * XSTR + c * 2);
            ah[2] = *(uint32_t*)(smc + OFF_XH + r * XSTR + (c + 8) * 2);
            ah[3] = *(uint32_t*)(smc + OFF_XH + (r + 8) * XSTR + (c + 8) * 2);
            al[0] = *(uint32_t*)(smc + OFF_XL + r * XSTR + c * 2);
            al[1] = *(uint32_t*)(smc + OFF_XL + (r + 8) * XSTR + c * 2);
            al[2] = *(uint32_t*)(smc + OFF_XL + r * XSTR + (c + 8) * 2);
            al[3] = *(uint32_t*)(smc + OFF_XL + (r + 8) * XSTR + (c + 8) * 2);
        }
        #pragma unroll
        for (int nt = 0; nt < 8; nt++) {
            const int bn = nt * 8 + qid, bk = k0 + qtr * 2;
            uint32_t bh[2], bl[2];
            bh[0] = *(uint32_t*)(smc + OFF_MH + bn * MSTR + bk * 2);
            bh[1] = *(uint32_t*)(smc + OFF_MH + bn * MSTR + (bk + 8) * 2);
            bl[0] = *(uint32_t*)(smc + OFF_ML + bn * MSTR + bk * 2);
            bl[1] = *(uint32_t*)(smc + OFF_ML + bn * MSTR + (bk + 8) * 2);
            mma16816(acc1[nt], ah, bh);
            mma16816(acc1[nt], ah, bl);
            mma16816(acc1[nt], al, bh);
        }
    }

    // ================= softmax + gate-fold (registers + quad shuffles) =============
    // acc1[nt][0,1] -> row r0+qid, cols 8nt+2qtr{+1};  [2,3] -> row r0+qid+8.
    float mxA = -1e30f, mxB = -1e30f;
    #pragma unroll
    for (int nt = 0; nt < 8; nt++) {
        mxA = fmaxf(mxA, fmaxf(acc1[nt][0], acc1[nt][1]));
        mxB = fmaxf(mxB, fmaxf(acc1[nt][2], acc1[nt][3]));
    }
    mxA = fmaxf(mxA, __shfl_xor_sync(0xffffffffu, mxA, 1));
    mxA = fmaxf(mxA, __shfl_xor_sync(0xffffffffu, mxA, 2));
    mxB = fmaxf(mxB, __shfl_xor_sync(0xffffffffu, mxB, 1));
    mxB = fmaxf(mxB, __shfl_xor_sync(0xffffffffu, mxB, 2));
    float smA = 0.f, smB = 0.f;
    #pragma unroll
    for (int nt = 0; nt < 8; nt++) {
        acc1[nt][0] = __expf(acc1[nt][0] - mxA);
        acc1[nt][1] = __expf(acc1[nt][1] - mxA);
        acc1[nt][2] = __expf(acc1[nt][2] - mxB);
        acc1[nt][3] = __expf(acc1[nt][3] - mxB);
        smA += acc1[nt][0] + acc1[nt][1];
        smB += acc1[nt][2] + acc1[nt][3];
    }
    smA += __shfl_xor_sync(0xffffffffu, smA, 1);
    smA += __shfl_xor_sync(0xffffffffu, smA, 2);
    smB += __shfl_xor_sync(0xffffffffu, smB, 1);
    smB += __shfl_xor_sync(0xffffffffu, smB, 2);
    const float gA = *(float*)(smc + OFF_GATE + 4 * (r0 + qid));
    const float gB = *(float*)(smc + OFF_GATE + 4 * (r0 + qid + 8));
    const float scA = gA / smA;         // fold g into attn -> GEMM2 yields g*read
    const float scB = gB / smB;

    // Convert to GEMM2 A-fragments (C-frag layout == A-frag layout, no SMEM bounce).
    uint32_t a2h[4][4], a2l[4][4];      // [k-step][frag reg]
    #pragma unroll
    for (int ks = 0; ks < 4; ks++) {
        #pragma unroll
        for (int half = 0; half < 2; half++) {      // half 0 -> regs 0,1 ; half 1 -> regs 2,3
            const int nt = 2 * ks + half;
            __nv_bfloat16 h0, l0, h1, l1, h2, l2, h3, l3;
            split2(acc1[nt][0] * scA, h0, l0);
            split2(acc1[nt][1] * scA, h1, l1);
            split2(acc1[nt][2] * scB, h2, l2);
            split2(acc1[nt][3] * scB, h3, l3);
            a2h[ks][2 * half]     = packbf(h0, h1);
            a2h[ks][2 * half + 1] = packbf(h2, h3);
            a2l[ks][2 * half]     = packbf(l0, l1);
            a2l[ks][2 * half + 1] = packbf(l2, l3);
        }
    }

    // ================= GEMM2: gRead[16 x 128] = (g*Attn) @ Mem  (bf16x3) ===========
    float acc2[16][4];
    #pragma unroll
    for (int nt = 0; nt < 16; nt++)
        #pragma unroll
        for (int j = 0; j < 4; j++) acc2[nt][j] = 0.f;

    #pragma unroll
    for (int ks = 0; ks < 4; ks++) {
        const int k0 = ks * 16;
        #pragma unroll
        for (int nt = 0; nt < 16; nt++) {
            const int bd = nt * 8 + qid, bm = k0 + qtr * 2;
            uint32_t bh[2], bl[2];
            bh[0] = *(uint32_t*)(smc + OFF_MTH + bd * MTSTR + bm * 2);
            bh[1] = *(uint32_t*)(smc + OFF_MTH + bd * MTSTR + (bm + 8) * 2);
            bl[0] = *(uint32_t*)(smc + OFF_MTL + bd * MTSTR + bm * 2);
            bl[1] = *(uint32_t*)(smc + OFF_MTL + bd * MTSTR + (bm + 8) * 2);
            mma16816(acc2[nt], a2h[ks], bh);
            mma16816(acc2[nt], a2h[ks], bl);
            mma16816(acc2[nt], a2l[ks], bh);
        }
    }
    __syncthreads();    // everyone done reading MH/ML/MTH/MTL -> STAGE may overwrite

    // ================= epilogue: out = (1-g)*x + gRead, via SMEM stage =============
    {
        float* stage = (float*)(smc + OFF_STAGE);
        const float ogA = 1.f - gA, ogB = 1.f - gB;
        const int rA = r0 + qid, rB = r0 + qid + 8;
        #pragma unroll
        for (int nt = 0; nt < 16; nt++) {
            const int c = nt * 8 + qtr * 2;
            uint32_t xhA = *(uint32_t*)(smc + OFF_XH + rA * XSTR + c * 2);
            uint32_t xlA = *(uint32_t*)(smc + OFF_XL + rA * XSTR + c * 2);
            uint32_t xhB = *(uint32_t*)(smc + OFF_XH + rB * XSTR + c * 2);
            uint32_t xlB = *(uint32_t*)(smc + OFF_XL + rB * XSTR + c * 2);
            __nv_bfloat162 hA = *(__nv_bfloat162*)&xhA, lA = *(__nv_bfloat162*)&xlA;
            __nv_bfloat162 hB = *(__nv_bfloat162*)&xhB, lB = *(__nv_bfloat162*)&xlB;
            float2 oA, oB;
            oA.x = ogA * (__bfloat162float(hA.x) + __bfloat162float(lA.x)) + acc2[nt][0];
            oA.y = ogA * (__bfloat162float(hA.y) + __bfloat162float(lA.y)) + acc2[nt][1];
            oB.x = ogB * (__bfloat162float(hB.x) + __bfloat162float(lB.x)) + acc2[nt][2];
            oB.y = ogB * (__bfloat162float(hB.y) + __bfloat162float(lB.y)) + acc2[nt][3];
            *(float2*)&stage[rA * STG_STR + c] = oA;
            *(float2*)&stage[rB * STG_STR + c] = oB;
        }
    }
    __syncthreads();
    {
        const float* stage = (const float*)(smc + OFF_STAGE);
        #pragma unroll
        for (int i = tid; i < TN * DDIM / 4; i += NTHREADS) {
            int n = i >> 5, q = i & 31;
            if (n0 + n < (long long)Ntot) {
                float4 v = *(const float4*)&stage[n * STG_STR + 4 * q];
                *(float4*)(out + (n0 + n) * DDIM + 4 * q) = v;
            }
        }
    }
}

extern "C" void kernel_launch(void* const* d_in, const int* in_sizes, int n_in,
                              void* d_out, int out_size)
{
    const float* x   = (const float*)d_in[0];
    const float* mem = (const float*)d_in[1];
    const float* gw  = (const float*)d_in[2];
    const float* gb  = (const float*)d_in[3];
    float* out = (float*)d_out;

    const int Ntot = in_sizes[0] / DDIM;
    const int grid = (Ntot + TN - 1) / TN;

    cudaFuncSetAttribute(gated_memory_hmma,
                         cudaFuncAttributeMaxDynamicSharedMemorySize, SMEM_BYTES);
    gated_memory_hmma<<<grid, NTHREADS, SMEM_BYTES>>>(x, mem, gw, gb, out, Ntot);
}

// round 11
// speedup vs baseline: 7.9733x; 1.8770x over previous
#include <cuda_runtime.h>
#include <cuda_bf16.h>
#include <cstdint>

// GatedMemoryModule via mma.sync (HMMA) + ldmatrix, bf16x3 split.
// out = g * softmax(x @ mem^T) @ mem + (1-g) * x,   g = sigmoid(x @ w + b)
// R10: 2 CTAs/SM (smem 105.5KB, regs capped via __launch_bounds__(256,2)):
//  - GEMM2 B-frags via ldmatrix.x4.trans on the row-major mem tiles (MT tiles gone)
//  - direct fragment STG.64 epilogue (stage buffer gone), 32B sectors fully used
//  - GEMM2 computed in two halves to keep acc2 at 32 live regs

#define TN       128
#define DDIM     128
#define MSLOT    64
#define NTHREADS 256

// bf16 row strides padded: stride % 128 == 16 bytes -> conflict-free ldmatrix rows.
#define XSTR   272
#define MSTR   272
#define OFF_XH   0                      // 128*272 = 34816
#define OFF_XL   34816
#define OFF_MH   69632                  // 64*272 = 17408
#define OFF_ML   87040
#define OFF_GATE 104448                 // 128 f32
#define OFF_GW   104960                 // 128 f32
#define SMEM_BYTES 105472

__device__ __forceinline__ void mma16816(float* d, const uint32_t* a, const uint32_t* b) {
    asm volatile(
        "mma.sync.aligned.m16n8k16.row.col.f32.bf16.bf16.f32 "
        "{%0,%1,%2,%3}, {%4,%5,%6,%7}, {%8,%9}, {%0,%1,%2,%3};"
        : "+f"(d[0]), "+f"(d[1]), "+f"(d[2]), "+f"(d[3])
        : "r"(a[0]), "r"(a[1]), "r"(a[2]), "r"(a[3]), "r"(b[0]), "r"(b[1]));
}
__device__ __forceinline__ void ldsm4(uint32_t* r, uint32_t a) {
    asm volatile("ldmatrix.sync.aligned.m8n8.x4.shared.b16 {%0,%1,%2,%3}, [%4];"
                 : "=r"(r[0]), "=r"(r[1]), "=r"(r[2]), "=r"(r[3]) : "r"(a));
}
__device__ __forceinline__ void ldsm4t(uint32_t* r, uint32_t a) {
    asm volatile("ldmatrix.sync.aligned.m8n8.x4.trans.shared.b16 {%0,%1,%2,%3}, [%4];"
                 : "=r"(r[0]), "=r"(r[1]), "=r"(r[2]), "=r"(r[3]) : "r"(a));
}
__device__ __forceinline__ uint32_t smem_u32(const void* p) {
    uint32_t a;
    asm("{ .reg .u64 t; cvta.to.shared.u64 t, %1; cvt.u32.u64 %0, t; }" : "=r"(a) : "l"(p));
    return a;
}
__device__ __forceinline__ void split2(float v, __nv_bfloat16& h, __nv_bfloat16& l) {
    h = __float2bfloat16(v);
    l = __float2bfloat16(v - __bfloat162float(h));
}
__device__ __forceinline__ uint32_t packbf(__nv_bfloat16 a, __nv_bfloat16 b) {
    __nv_bfloat162 p; p.x = a; p.y = b;
    return *(uint32_t*)&p;
}

extern __shared__ char smc[];

__global__ void __launch_bounds__(NTHREADS, 2)
gated_memory_hmma(const float* __restrict__ x, const float* __restrict__ mem,
                  const float* __restrict__ gw, const float* __restrict__ gb,
                  float* __restrict__ out, int Ntot)
{
    const int tid = threadIdx.x;
    const int wid = tid >> 5;
    const int lane = tid & 31;
    const int qid = lane >> 2;
    const int qtr = lane & 3;
    const long long n0 = (long long)blockIdx.x * TN;
    const uint32_t sb = smem_u32(smc);

    // ===== Phase 0: stage X and Mem as bf16 hi/lo tiles =====
    {
        const float4* x4 = (const float4*)x;
        #pragma unroll
        for (int i = tid; i < TN * DDIM / 4; i += NTHREADS) {
            int n = i >> 5, q = i & 31;
            float4 v = make_float4(0.f, 0.f, 0.f, 0.f);
            if (n0 + n < (long long)Ntot) v = x4[(n0 + n) * (DDIM / 4) + q];
            float vv[4] = {v.x, v.y, v.z, v.w};
            __nv_bfloat16 h[4], l[4];
            #pragma unroll
            for (int j = 0; j < 4; j++) split2(vv[j], h[j], l[j]);
            char* ph = smc + OFF_XH + n * XSTR + q * 8;
            char* pl = smc + OFF_XL + n * XSTR + q * 8;
            ((uint32_t*)ph)[0] = packbf(h[0], h[1]); ((uint32_t*)ph)[1] = packbf(h[2], h[3]);
            ((uint32_t*)pl)[0] = packbf(l[0], l[1]); ((uint32_t*)pl)[1] = packbf(l[2], l[3]);
        }
        const float4* m4 = (const float4*)mem;
        #pragma unroll
        for (int i = tid; i < MSLOT * DDIM / 4; i += NTHREADS) {
            int m = i >> 5, q = i & 31;
            float4 v = m4[i];
            float vv[4] = {v.x, v.y, v.z, v.w};
            __nv_bfloat16 h[4], l[4];
            #pragma unroll
            for (int j = 0; j < 4; j++) split2(vv[j], h[j], l[j]);
            char* ph = smc + OFF_MH + m * MSTR + q * 8;
            char* pl = smc + OFF_ML + m * MSTR + q * 8;
            ((uint32_t*)ph)[0] = packbf(h[0], h[1]); ((uint32_t*)ph)[1] = packbf(h[2], h[3]);
            ((uint32_t*)pl)[0] = packbf(l[0], l[1]); ((uint32_t*)pl)[1] = packbf(l[2], l[3]);
        }
        if (tid < DDIM) *(float*)(smc + OFF_GW + 4 * tid) = gw[tid];
    }
    __syncthreads();

    // ===== gate: g[n] = sigmoid(x[n].w + b) =====
    if (tid < TN) {
        float acc = 0.f;
        #pragma unroll 16
        for (int c = 0; c < DDIM; c += 2) {
            __nv_bfloat162 hv = *(__nv_bfloat162*)(smc + OFF_XH + tid * XSTR + c * 2);
            __nv_bfloat162 lv = *(__nv_bfloat162*)(smc + OFF_XL + tid * XSTR + c * 2);
            float2 wv = *(float2*)(smc + OFF_GW + 4 * c);
            acc += (__bfloat162float(hv.x) + __bfloat162float(lv.x)) * wv.x
                 + (__bfloat162float(hv.y) + __bfloat162float(lv.y)) * wv.y;
        }
        float g = 1.f / (1.f + __expf(-(acc + gb[0])));
        *(float*)(smc + OFF_GATE + 4 * tid) = g;
    }
    __syncthreads();

    const int r0 = wid * 16;

    // ldmatrix per-lane base addresses (lane -> matrix j = lane>>3, row = lane&7)
    const int Lm8 = lane & 7, j = lane >> 3;
    // A (non-trans): j0:(r0,k0) j1:(r0+8,k0) j2:(r0,k0+8) j3:(r0+8,k0+8)
    const uint32_t aBase = sb + OFF_XH + (uint32_t)((r0 + Lm8 + 8 * (j & 1)) * XSTR + (8 * (j >> 1)) * 2);
    // GEMM1 B (non-trans): j0:b0(nt=2p) j1:b1(nt=2p) j2:b0(nt=2p+1) j3:b1(nt=2p+1)
    const uint32_t bBase = sb + OFF_MH + (uint32_t)((Lm8 + 8 * (j >> 1)) * MSTR + (8 * (j & 1)) * 2);
    // GEMM2 B (trans): rows are mem m-rows; j0:b0(nt=2p) j1:b1(nt=2p) j2:b0(2p+1) j3:b1(2p+1)
    const uint32_t btBase = sb + OFF_MH + (uint32_t)((Lm8 + 8 * (j & 1)) * MSTR + (8 * (j >> 1)) * 2);

    // ===== GEMM1: S[16 x 64] = X @ Mem^T (bf16x3) =====
    float acc1[8][4];
    #pragma unroll
    for (int nt = 0; nt < 8; nt++)
        #pragma unroll
        for (int jj = 0; jj < 4; jj++) acc1[nt][jj] = 0.f;

    #pragma unroll
    for (int ks = 0; ks < 8; ks++) {
        uint32_t ah[4], al[4];
        ldsm4(ah, aBase + ks * 32);
        ldsm4(al, aBase + ks * 32 + (OFF_XL - OFF_XH));
        #pragma unroll
        for (int p = 0; p < 4; p++) {
            uint32_t bh[4], bl[4];
            uint32_t addr = bBase + (uint32_t)(p * 16 * MSTR) + ks * 32;
            ldsm4(bh, addr);
            ldsm4(bl, addr + (OFF_ML - OFF_MH));
            mma16816(acc1[2 * p],     ah, bh);
            mma16816(acc1[2 * p],     ah, bl + 0);
            mma16816(acc1[2 * p],     al, bh);
            mma16816(acc1[2 * p + 1], ah, bh + 2);
            mma16816(acc1[2 * p + 1], ah, bl + 2);
            mma16816(acc1[2 * p + 1], al, bh + 2);
        }
    }

    // ===== softmax + gate fold (registers + quad shuffles) =====
    float mxA = -1e30f, mxB = -1e30f;
    #pragma unroll
    for (int nt = 0; nt < 8; nt++) {
        mxA = fmaxf(mxA, fmaxf(acc1[nt][0], acc1[nt][1]));
        mxB = fmaxf(mxB, fmaxf(acc1[nt][2], acc1[nt][3]));
    }
    mxA = fmaxf(mxA, __shfl_xor_sync(0xffffffffu, mxA, 1));
    mxA = fmaxf(mxA, __shfl_xor_sync(0xffffffffu, mxA, 2));
    mxB = fmaxf(mxB, __shfl_xor_sync(0xffffffffu, mxB, 1));
    mxB = fmaxf(mxB, __shfl_xor_sync(0xffffffffu, mxB, 2));
    float smA = 0.f, smB = 0.f;
    #pragma unroll
    for (int nt = 0; nt < 8; nt++) {
        acc1[nt][0] = __expf(acc1[nt][0] - mxA);
        acc1[nt][1] = __expf(acc1[nt][1] - mxA);
        acc1[nt][2] = __expf(acc1[nt][2] - mxB);
        acc1[nt][3] = __expf(acc1[nt][3] - mxB);
        smA += acc1[nt][0] + acc1[nt][1];
        smB += acc1[nt][2] + acc1[nt][3];
    }
    smA += __shfl_xor_sync(0xffffffffu, smA, 1);
    smA += __shfl_xor_sync(0xffffffffu, smA, 2);
    smB += __shfl_xor_sync(0xffffffffu, smB, 1);
    smB += __shfl_xor_sync(0xffffffffu, smB, 2);
    const float gA = *(float*)(smc + OFF_GATE + 4 * (r0 + qid));
    const float gB = *(float*)(smc + OFF_GATE + 4 * (r0 + qid + 8));
    const float scA = gA / smA;     // fold g into attn -> GEMM2 yields g*read
    const float scB = gB / smB;
    const float ogA = 1.f - gA, ogB = 1.f - gB;

    // C-frag layout == A-frag layout: convert in registers.
    uint32_t a2h[4][4], a2l[4][4];
    #pragma unroll
    for (int ks = 0; ks < 4; ks++) {
        #pragma unroll
        for (int half = 0; half < 2; half++) {
            const int nt = 2 * ks + half;
            __nv_bfloat16 h0, l0, h1, l1, h2, l2, h3, l3;
            split2(acc1[nt][0] * scA, h0, l0);
            split2(acc1[nt][1] * scA, h1, l1);
            split2(acc1[nt][2] * scB, h2, l2);
            split2(acc1[nt][3] * scB, h3, l3);
            a2h[ks][2 * half]     = packbf(h0, h1);
            a2h[ks][2 * half + 1] = packbf(h2, h3);
            a2l[ks][2 * half]     = packbf(l0, l1);
            a2l[ks][2 * half + 1] = packbf(l2, l3);
        }
    }

    // ===== GEMM2 (two halves of 64 d-cols) + fused fragment epilogue =====
    const int rA = r0 + qid, rB = rA + 8;
    const bool okA = (n0 + rA < (long long)Ntot), okB = (n0 + rB < (long long)Ntot);
    float* outA = out + (n0 + rA) * DDIM;
    float* outB = out + (n0 + rB) * DDIM;

    #pragma unroll
    for (int h = 0; h < 2; h++) {
        float acc2[8][4];
        #pragma unroll
        for (int nt = 0; nt < 8; nt++)
            #pragma unroll
            for (int jj = 0; jj < 4; jj++) acc2[nt][jj] = 0.f;

        #pragma unroll
        for (int ks = 0; ks < 4; ks++) {
            const uint32_t rowAddr = btBase + (uint32_t)(ks * 16 * MSTR);
            #pragma unroll
            for (int p = 0; p < 4; p++) {
                uint32_t bh[4], bl[4];
                uint32_t addr = rowAddr + (uint32_t)((4 * h + p) * 32);
                ldsm4t(bh, addr);
                ldsm4t(bl, addr + (OFF_ML - OFF_MH));
                mma16816(acc2[2 * p],     a2h[ks], bh);
                mma16816(acc2[2 * p],     a2h[ks], bl + 0);
                mma16816(acc2[2 * p],     a2l[ks], bh);
                mma16816(acc2[2 * p + 1], a2h[ks], bh + 2);
                mma16816(acc2[2 * p + 1], a2h[ks], bl + 2);
                mma16816(acc2[2 * p + 1], a2l[ks], bh + 2);
            }
        }

        // epilogue for this half: out = (1-g)*x + g*read  (32B sectors fully used)
        #pragma unroll
        for (int nt = 0; nt < 8; nt++) {
            const int c = (8 * h + nt) * 8 + qtr * 2;
            uint32_t xhA = *(uint32_t*)(smc + OFF_XH + rA * XSTR + c * 2);
            uint32_t xlA = *(uint32_t*)(smc + OFF_XL + rA * XSTR + c * 2);
            uint32_t xhB = *(uint32_t*)(smc + OFF_XH + rB * XSTR + c * 2);
            uint32_t xlB = *(uint32_t*)(smc + OFF_XL + rB * XSTR + c * 2);
            __nv_bfloat162 hA = *(__nv_bfloat162*)&xhA, lA = *(__nv_bfloat162*)&xlA;
            __nv_bfloat162 hB = *(__nv_bfloat162*)&xhB, lB = *(__nv_bfloat162*)&xlB;
            float2 oA, oB;
            oA.x = ogA * (__bfloat162float(hA.x) + __bfloat162float(lA.x)) + acc2[nt][0];
            oA.y = ogA * (__bfloat162float(hA.y) + __bfloat162float(lA.y)) + acc2[nt][1];
            oB.x = ogB * (__bfloat162float(hB.x) + __bfloat162float(lB.x)) + acc2[nt][2];
            oB.y = ogB * (__bfloat162float(hB.y) + __bfloat162float(lB.y)) + acc2[nt][3];
            if (okA) *(float2*)(outA + c) = oA;
            if (okB) *(float2*)(outB + c) = oB;
        }
    }
}

extern "C" void kernel_launch(void* const* d_in, const int* in_sizes, int n_in,
                              void* d_out, int out_size)
{
    const float* x   = (const float*)d_in[0];
    const float* mem = (const float*)d_in[1];
    const float* gw  = (const float*)d_in[2];
    const float* gb  = (const float*)d_in[3];
    float* out = (float*)d_out;

    const int Ntot = in_sizes[0] / DDIM;
    const int grid = (Ntot + TN - 1) / TN;

    cudaFuncSetAttribute(gated_memory_hmma,
                         cudaFuncAttributeMaxDynamicSharedMemorySize, SMEM_BYTES);
    gated_memory_hmma<<<grid, NTHREADS, SMEM_BYTES>>>(x, mem, gw, gb, out, Ntot);
}

// round 13
// speedup vs baseline: 9.4610x; 1.1866x over previous
#include <cuda_runtime.h>
#include <cuda_fp16.h>
#include <cstdint>

// GatedMemoryModule via mma.sync (HMMA) + ldmatrix, fp16 multi-pass split.
// out = g * softmax(x @ mem^T) @ mem + (1-g) * x,   g = sigmoid(x @ w + b)
// R12: fp16 operands (11-bit mantissa):
//  - GEMM1 3-pass (hi*hi + hi*lo + lo*hi), residual ~2^-22 -> sim err negligible
//  - GEMM2 2-pass ((a_hi + a_lo) * m_hi), read err ~2.8e-4 rel -> drops 64 MMAs
//    and all GEMM2 lo-tile ldmatrix loads per warp
//  - gate dot folded into the staging loop (warp covers one row per iteration:
//    float4 partial + 5x shfl.bfly, lane0 stores) -- serial gate phase removed

#define TN       128
#define DDIM     128
#define MSLOT    64
#define NTHREADS 256

// fp16 row strides padded: stride % 128 == 16 bytes -> conflict-free ldmatrix rows.
#define XSTR   272
#define MSTR   272
#define OFF_XH   0                      // 128*272 = 34816
#define OFF_XL   34816
#define OFF_MH   69632                  // 64*272 = 17408
#define OFF_ML   87040                  // -> 104448
#define OFF_GATE 104448                 // 128 f32 (raw gate dot)
#define SMEM_BYTES 104960

__device__ __forceinline__ void mma16816(float* d, const uint32_t* a, const uint32_t* b) {
    asm volatile(
        "mma.sync.aligned.m16n8k16.row.col.f32.f16.f16.f32 "
        "{%0,%1,%2,%3}, {%4,%5,%6,%7}, {%8,%9}, {%0,%1,%2,%3};"
        : "+f"(d[0]), "+f"(d[1]), "+f"(d[2]), "+f"(d[3])
        : "r"(a[0]), "r"(a[1]), "r"(a[2]), "r"(a[3]), "r"(b[0]), "r"(b[1]));
}
__device__ __forceinline__ void ldsm4(uint32_t* r, uint32_t a) {
    asm volatile("ldmatrix.sync.aligned.m8n8.x4.shared.b16 {%0,%1,%2,%3}, [%4];"
                 : "=r"(r[0]), "=r"(r[1]), "=r"(r[2]), "=r"(r[3]) : "r"(a));
}
__device__ __forceinline__ void ldsm4t(uint32_t* r, uint32_t a) {
    asm volatile("ldmatrix.sync.aligned.m8n8.x4.trans.shared.b16 {%0,%1,%2,%3}, [%4];"
                 : "=r"(r[0]), "=r"(r[1]), "=r"(r[2]), "=r"(r[3]) : "r"(a));
}
__device__ __forceinline__ uint32_t smem_u32(const void* p) {
    uint32_t a;
    asm("{ .reg .u64 t; cvta.to.shared.u64 t, %1; cvt.u32.u64 %0, t; }" : "=r"(a) : "l"(p));
    return a;
}
__device__ __forceinline__ void split2h(float v, __half& h, __half& l) {
    h = __float2half_rn(v);
    l = __float2half_rn(v - __half2float(h));
}
__device__ __forceinline__ uint32_t packh(__half a, __half b) {
    __half2 p; p.x = a; p.y = b;
    return *(uint32_t*)&p;
}

extern __shared__ char smc[];

__global__ void __launch_bounds__(NTHREADS, 2)
gated_memory_hmma(const float* __restrict__ x, const float* __restrict__ mem,
                  const float* __restrict__ gw, const float* __restrict__ gb,
                  float* __restrict__ out, int Ntot)
{
    const int tid = threadIdx.x;
    const int wid = tid >> 5;
    const int lane = tid & 31;
    const int qid = lane >> 2;
    const int qtr = lane & 3;
    const long long n0 = (long long)blockIdx.x * TN;
    const uint32_t sb = smem_u32(smc);
    const float gb0 = gb[0];

    // ===== Phase 0: stage X/Mem as fp16 hi/lo tiles; gate dot folded in =====
    {
        // In the x loop, iteration 'it' has the whole warp on row n = wid + 8*it
        // and q == lane, so w fragment per thread is fixed:
        const float4 wreg = ((const float4*)gw)[lane];
        const float4* x4 = (const float4*)x;
        #pragma unroll
        for (int i = tid; i < TN * DDIM / 4; i += NTHREADS) {
            int n = i >> 5, q = i & 31;
            float4 v = make_float4(0.f, 0.f, 0.f, 0.f);
            if (n0 + n < (long long)Ntot) v = x4[(n0 + n) * (DDIM / 4) + q];
            float vv[4] = {v.x, v.y, v.z, v.w};
            __half h[4], l[4];
            #pragma unroll
            for (int j = 0; j < 4; j++) split2h(vv[j], h[j], l[j]);
            char* ph = smc + OFF_XH + n * XSTR + q * 8;
            char* pl = smc + OFF_XL + n * XSTR + q * 8;
            ((uint32_t*)ph)[0] = packh(h[0], h[1]); ((uint32_t*)ph)[1] = packh(h[2], h[3]);
            ((uint32_t*)pl)[0] = packh(l[0], l[1]); ((uint32_t*)pl)[1] = packh(l[2], l[3]);
            // gate partial: x[n][4q..4q+3] . w[4q..4q+3], warp-reduce (one row/warp)
            float part = v.x * wreg.x + v.y * wreg.y + v.z * wreg.z + v.w * wreg.w;
            part += __shfl_xor_sync(0xffffffffu, part, 16);
            part += __shfl_xor_sync(0xffffffffu, part, 8);
            part += __shfl_xor_sync(0xffffffffu, part, 4);
            part += __shfl_xor_sync(0xffffffffu, part, 2);
            part += __shfl_xor_sync(0xffffffffu, part, 1);
            if (lane == 0) *(float*)(smc + OFF_GATE + 4 * n) = part;
        }
        const float4* m4 = (const float4*)mem;
        #pragma unroll
        for (int i = tid; i < MSLOT * DDIM / 4; i += NTHREADS) {
            int m = i >> 5, q = i & 31;
            float4 v = m4[i];
            float vv[4] = {v.x, v.y, v.z, v.w};
            __half h[4], l[4];
            #pragma unroll
            for (int j = 0; j < 4; j++) split2h(vv[j], h[j], l[j]);
            char* ph = smc + OFF_MH + m * MSTR + q * 8;
            char* pl = smc + OFF_ML + m * MSTR + q * 8;
            ((uint32_t*)ph)[0] = packh(h[0], h[1]); ((uint32_t*)ph)[1] = packh(h[2], h[3]);
            ((uint32_t*)pl)[0] = packh(l[0], l[1]); ((uint32_t*)pl)[1] = packh(l[2], l[3]);
        }
    }
    __syncthreads();

    const int r0 = wid * 16;

    // ldmatrix per-lane base addresses (lane -> matrix j = lane>>3, row = lane&7)
    const int Lm8 = lane & 7, j = lane >> 3;
    // A (non-trans): j0:(r0,k0) j1:(r0+8,k0) j2:(r0,k0+8) j3:(r0+8,k0+8)
    const uint32_t aBase = sb + OFF_XH + (uint32_t)((r0 + Lm8 + 8 * (j & 1)) * XSTR + (8 * (j >> 1)) * 2);
    // GEMM1 B (non-trans)
    const uint32_t bBase = sb + OFF_MH + (uint32_t)((Lm8 + 8 * (j >> 1)) * MSTR + (8 * (j & 1)) * 2);
    // GEMM2 B (trans): rows are mem m-rows
    const uint32_t btBase = sb + OFF_MH + (uint32_t)((Lm8 + 8 * (j & 1)) * MSTR + (8 * (j >> 1)) * 2);

    // ===== GEMM1: S[16 x 64] = X @ Mem^T (fp16 3-pass) =====
    float acc1[8][4];
    #pragma unroll
    for (int nt = 0; nt < 8; nt++)
        #pragma unroll
        for (int jj = 0; jj < 4; jj++) acc1[nt][jj] = 0.f;

    #pragma unroll
    for (int ks = 0; ks < 8; ks++) {
        uint32_t ah[4], al[4];
        ldsm4(ah, aBase + ks * 32);
        ldsm4(al, aBase + ks * 32 + (OFF_XL - OFF_XH));
        #pragma unroll
        for (int p = 0; p < 4; p++) {
            uint32_t bh[4], bl[4];
            uint32_t addr = bBase + (uint32_t)(p * 16 * MSTR) + ks * 32;
            ldsm4(bh, addr);
            ldsm4(bl, addr + (OFF_ML - OFF_MH));
            mma16816(acc1[2 * p],     ah, bh);
            mma16816(acc1[2 * p],     ah, bl + 0);
            mma16816(acc1[2 * p],     al, bh);
            mma16816(acc1[2 * p + 1], ah, bh + 2);
            mma16816(acc1[2 * p + 1], ah, bl + 2);
            mma16816(acc1[2 * p + 1], al, bh + 2);
        }
    }

    // ===== softmax + gate fold (registers + quad shuffles) =====
    float mxA = -1e30f, mxB = -1e30f;
    #pragma unroll
    for (int nt = 0; nt < 8; nt++) {
        mxA = fmaxf(mxA, fmaxf(acc1[nt][0], acc1[nt][1]));
        mxB = fmaxf(mxB, fmaxf(acc1[nt][2], acc1[nt][3]));
    }
    mxA = fmaxf(mxA, __shfl_xor_sync(0xffffffffu, mxA, 1));
    mxA = fmaxf(mxA, __shfl_xor_sync(0xffffffffu, mxA, 2));
    mxB = fmaxf(mxB, __shfl_xor_sync(0xffffffffu, mxB, 1));
    mxB = fmaxf(mxB, __shfl_xor_sync(0xffffffffu, mxB, 2));
    float smA = 0.f, smB = 0.f;
    #pragma unroll
    for (int nt = 0; nt < 8; nt++) {
        acc1[nt][0] = __expf(acc1[nt][0] - mxA);
        acc1[nt][1] = __expf(acc1[nt][1] - mxA);
        acc1[nt][2] = __expf(acc1[nt][2] - mxB);
        acc1[nt][3] = __expf(acc1[nt][3] - mxB);
        smA += acc1[nt][0] + acc1[nt][1];
        smB += acc1[nt][2] + acc1[nt][3];
    }
    smA += __shfl_xor_sync(0xffffffffu, smA, 1);
    smA += __shfl_xor_sync(0xffffffffu, smA, 2);
    smB += __shfl_xor_sync(0xffffffffu, smB, 1);
    smB += __shfl_xor_sync(0xffffffffu, smB, 2);
    const float gdA = *(float*)(smc + OFF_GATE + 4 * (r0 + qid));
    const float gdB = *(float*)(smc + OFF_GATE + 4 * (r0 + qid + 8));
    const float gA = 1.f / (1.f + __expf(-(gdA + gb0)));
    const float gB = 1.f / (1.f + __expf(-(gdB + gb0)));
    const float scA = gA / smA;     // fold g into attn -> GEMM2 yields g*read
    const float scB = gB / smB;
    const float ogA = 1.f - gA, ogB = 1.f - gB;

    // C-frag layout == A-frag layout: convert in registers (fp16 hi/lo).
    uint32_t a2h[4][4], a2l[4][4];
    #pragma unroll
    for (int ks = 0; ks < 4; ks++) {
        #pragma unroll
        for (int half = 0; half < 2; half++) {
            const int nt = 2 * ks + half;
            __half h0, l0, h1, l1, h2, l2, h3, l3;
            split2h(acc1[nt][0] * scA, h0, l0);
            split2h(acc1[nt][1] * scA, h1, l1);
            split2h(acc1[nt][2] * scB, h2, l2);
            split2h(acc1[nt][3] * scB, h3, l3);
            a2h[ks][2 * half]     = packh(h0, h1);
            a2h[ks][2 * half + 1] = packh(h2, h3);
            a2l[ks][2 * half]     = packh(l0, l1);
            a2l[ks][2 * half + 1] = packh(l2, l3);
        }
    }

    // ===== GEMM2 (fp16 2-pass, hi mem tile only) + fused fragment epilogue =====
    const int rA = r0 + qid, rB = rA + 8;
    const bool okA = (n0 + rA < (long long)Ntot), okB = (n0 + rB < (long long)Ntot);
    float* outA = out + (n0 + rA) * DDIM;
    float* outB = out + (n0 + rB) * DDIM;

    #pragma unroll
    for (int h = 0; h < 2; h++) {
        float acc2[8][4];
        #pragma unroll
        for (int nt = 0; nt < 8; nt++)
            #pragma unroll
            for (int jj = 0; jj < 4; jj++) acc2[nt][jj] = 0.f;

        #pragma unroll
        for (int ks = 0; ks < 4; ks++) {
            const uint32_t rowAddr = btBase + (uint32_t)(ks * 16 * MSTR);
            #pragma unroll
            for (int p = 0; p < 4; p++) {
                uint32_t bh[4];
                ldsm4t(bh, rowAddr + (uint32_t)((4 * h + p) * 32));
                mma16816(acc2[2 * p],     a2h[ks], bh);
                mma16816(acc2[2 * p],     a2l[ks], bh);
                mma16816(acc2[2 * p + 1], a2h[ks], bh + 2);
                mma16816(acc2[2 * p + 1], a2l[ks], bh + 2);
            }
        }

        // epilogue for this half: out = (1-g)*x + g*read
        #pragma unroll
        for (int nt = 0; nt < 8; nt++) {
            const int c = (8 * h + nt) * 8 + qtr * 2;
            uint32_t xhA = *(uint32_t*)(smc + OFF_XH + rA * XSTR + c * 2);
            uint32_t xlA = *(uint32_t*)(smc + OFF_XL + rA * XSTR + c * 2);
            uint32_t xhB = *(uint32_t*)(smc + OFF_XH + rB * XSTR + c * 2);
            uint32_t xlB = *(uint32_t*)(smc + OFF_XL + rB * XSTR + c * 2);
            float2 hA = __half22float2(*(__half2*)&xhA), lA = __half22float2(*(__half2*)&xlA);
            float2 hB = __half22float2(*(__half2*)&xhB), lB = __half22float2(*(__half2*)&xlB);
            float2 oA, oB;
            oA.x = ogA * (hA.x + lA.x) + acc2[nt][0];
            oA.y = ogA * (hA.y + lA.y) + acc2[nt][1];
            oB.x = ogB * (hB.x + lB.x) + acc2[nt][2];
            oB.y = ogB * (hB.y + lB.y) + acc2[nt][3];
            if (okA) *(float2*)(outA + c) = oA;
            if (okB) *(float2*)(outB + c) = oB;
        }
    }
}

extern "C" void kernel_launch(void* const* d_in, const int* in_sizes, int n_in,
                              void* d_out, int out_size)
{
    const float* x   = (const float*)d_in[0];
    const float* mem = (const float*)d_in[1];
    const float* gw  = (const float*)d_in[2];
    const float* gb  = (const float*)d_in[3];
    float* out = (float*)d_out;

    const int Ntot = in_sizes[0] / DDIM;
    const int grid = (Ntot + TN - 1) / TN;

    cudaFuncSetAttribute(gated_memory_hmma,
                         cudaFuncAttributeMaxDynamicSharedMemorySize, SMEM_BYTES);
    gated_memory_hmma<<<grid, NTHREADS, SMEM_BYTES>>>(x, mem, gw, gb, out, Ntot);
}